// round 10
// baseline (speedup 1.0000x reference)
#include <cuda_runtime.h>
#include <math.h>
#include <stdint.h>

// Shapes: T_FAST=512, T_SLOW=128, B=32, D=1024, H=256
// Inputs: 0..3 feat[T,B,D] f32; 4 mlp_w1[16,2048,256]; 5 mlp_b1[16,256];
// 6 mlp_w2[16,256,1]; 7 mlp_b2[16,1]; 8 s2f_w[1024,1024,1]; 9 s2f_b[1024];
// 10 f2s_w[4,1024,1024,5]
// Output: concat(out0[512,32,1024], out1, out2[128,32,1024], out3) f32

#define BATCH 32
#define DDIM  1024

// ---------------- scratch ----------------
static __device__ float g_means[4][BATCH][DDIM];
static __device__ float g_score[16][BATCH];
static __device__ __align__(128) float g_y[2][128 * BATCH * DDIM];   // s2f out, 33.5 MB
static __device__ __align__(128) float g_wB[2][1024 * 5120];         // f2s W fragment-packed, 42 MB
static __device__ __align__(128) float g_wS[1024 * 1024];            // s2f W fragment-packed, 4 MB

__constant__ int c_api[8] = {2, 2, 3, 3, 0, 0, 1, 1};
__constant__ int c_apj[8] = {0, 1, 0, 1, 2, 3, 2, 3};

// ---------------- helpers ----------------
__device__ __forceinline__ float to_tf32(float x) {
    uint32_t u; asm("cvt.rna.tf32.f32 %0, %1;" : "=r"(u) : "f"(x));
    return __uint_as_float(u);
}
__device__ __forceinline__ uint32_t smem_u32(const void* p) {
    return (uint32_t)__cvta_generic_to_shared(p);
}
__device__ __forceinline__ void cp16(uint32_t dst, const void* src, int sz) {
    asm volatile("cp.async.ca.shared.global [%0], [%1], 16, %2;" :: "r"(dst), "l"(src), "r"(sz));
}
__device__ __forceinline__ void cp_commit() { asm volatile("cp.async.commit_group;"); }
template <int N> __device__ __forceinline__ void cp_wait() {
    asm volatile("cp.async.wait_group %0;" :: "n"(N));
}
__device__ __forceinline__ void mma_tf32(float (&c)[4], uint32_t a0, uint32_t a1, uint32_t a2,
                                         uint32_t a3, uint32_t b0, uint32_t b1) {
    asm("mma.sync.aligned.m16n8k8.row.col.f32.tf32.tf32.f32 "
        "{%0,%1,%2,%3},{%4,%5,%6,%7},{%8,%9},{%0,%1,%2,%3};"
        : "+f"(c[0]), "+f"(c[1]), "+f"(c[2]), "+f"(c[3])
        : "r"(a0), "r"(a1), "r"(a2), "r"(a3), "r"(b0), "r"(b1));
}
#define LDSM4(r, a) \
    asm volatile("ldmatrix.sync.aligned.m8n8.x4.shared.b16 {%0,%1,%2,%3}, [%4];" \
        : "=r"((r)[0]), "=r"((r)[1]), "=r"((r)[2]), "=r"((r)[3]) : "r"(a))
#define LDS128(r, a) \
    asm volatile("ld.shared.v4.b32 {%0,%1,%2,%3}, [%4];" \
        : "=r"((r)[0]), "=r"((r)[1]), "=r"((r)[2]), "=r"((r)[3]) : "r"(a))

// Per-block gate-selection recompute.
#define BLOCK_SELECT(jj, tid, s_sel, s_score) do { \
    if ((tid) < 32) { \
        int pA_, pB_, iA_, iB_; \
        if ((jj) < 2) { pA_ = 12 + (jj); iA_ = 3; pB_ = 8 + (jj); iB_ = 2; } \
        else          { pA_ = 4 + (jj);  iA_ = 1; pB_ = (jj);     iB_ = 0; } \
        float sA_ = g_score[pA_][(tid)], sB_ = g_score[pB_][(tid)]; \
        float mA_ = sA_, mB_ = sB_; \
        for (int o_ = 16; o_ > 0; o_ >>= 1) { \
            mA_ += __shfl_xor_sync(0xffffffffu, mA_, o_); \
            mB_ += __shfl_xor_sync(0xffffffffu, mB_, o_); \
        } \
        bool cA_ = (mA_ * (1.f / 32.f)) >= 0.3f; \
        bool cB_ = (mB_ * (1.f / 32.f)) >= 0.3f; \
        if ((tid) == 0) s_sel = cA_ ? iA_ : (cB_ ? iB_ : -1); \
        s_score[(tid)] = cA_ ? sA_ : (cB_ ? sB_ : 0.f); \
    } \
    __syncthreads(); \
} while (0)

// GEMM tiling: CTA = 128 n x 128 dout, BK = 32, 128 threads (4 warps 2x2: wm=wid&1, wn=wid>>1)
// Warp tile 64n x 64d. 3-stage cp.async ring; 2 CTAs/SM.
// A smem: [128 rows][36 floats] (32 used + 4 pad) = 18432 B/stage  (LDSM banks: r*36%32 = 4r, CF)
// B smem: frag-packed 4096 floats = 16384 B/stage
// B chunk (4096 floats): [ks(4)][kh(2)][wn(2)][grp(8)][tg(4)][sl(1)][n4(4)]
//   physical slot sl holds niq = sl ^ (grp&1)  (bank-conflict-free phase coverage)
//   value = W[dout = wn*64 + (niq*4+n4)*8 + grp][k = ks*8 + kh*4 + tg]   (k within 32-K tile)
#define ASTAGE 18432
#define BSTAGE 16384
#define NSTAGE 3
#define GSMEM  (NSTAGE * (ASTAGE + BSTAGE))

// ---------------- 1) means ----------------
__global__ void means_kernel(const float* __restrict__ f0, const float* __restrict__ f1,
                             const float* __restrict__ f2, const float* __restrict__ f3) {
    int z = blockIdx.y;
    const float* f = (z == 0) ? f0 : (z == 1) ? f1 : (z == 2) ? f2 : f3;
    int T = (z < 2) ? 512 : 128;
    int idx = blockIdx.x * blockDim.x + threadIdx.x;
    if (idx >= BATCH * DDIM) return;
    float s0 = 0.f, s1 = 0.f, s2 = 0.f, s3 = 0.f;
    const float* p = f + idx;
    const int STRIDE = BATCH * DDIM;
    #pragma unroll 4
    for (int t = 0; t < T; t += 4) {
        s0 += p[(size_t)(t + 0) * STRIDE];
        s1 += p[(size_t)(t + 1) * STRIDE];
        s2 += p[(size_t)(t + 2) * STRIDE];
        s3 += p[(size_t)(t + 3) * STRIDE];
    }
    (&g_means[z][0][0])[idx] = ((s0 + s1) + (s2 + s3)) * (1.0f / (float)T);
}

// ---------------- 2) pair-gate MLPs -> g_score ----------------
__global__ void mlp_kernel(const float* __restrict__ w1, const float* __restrict__ b1,
                           const float* __restrict__ w2, const float* __restrict__ b2) {
    __shared__ float vec[4][2048];
    __shared__ float red[4][256];
    int pi = blockIdx.x, bg = blockIdx.y;
    int i = c_api[pi], j = c_apj[pi];
    int p = i * 4 + j;
    int tid = threadIdx.x;
    for (int q = 0; q < 4; ++q) {
        int b = bg * 4 + q;
        for (int k = tid; k < 2048; k += 256)
            vec[q][k] = (k < 1024) ? g_means[i][b][k] : g_means[j][b][k - 1024];
    }
    __syncthreads();
    const float* w1p = w1 + (size_t)p * 2048 * 256 + tid;
    float a0 = 0.f, a1 = 0.f, a2 = 0.f, a3 = 0.f;
    #pragma unroll 4
    for (int k = 0; k < 2048; ++k) {
        float w = w1p[(size_t)k * 256];
        a0 = fmaf(vec[0][k], w, a0);
        a1 = fmaf(vec[1][k], w, a1);
        a2 = fmaf(vec[2][k], w, a2);
        a3 = fmaf(vec[3][k], w, a3);
    }
    float bb = b1[p * 256 + tid];
    float wv = w2[p * 256 + tid];
    red[0][tid] = fmaxf(a0 + bb, 0.f) * wv;
    red[1][tid] = fmaxf(a1 + bb, 0.f) * wv;
    red[2][tid] = fmaxf(a2 + bb, 0.f) * wv;
    red[3][tid] = fmaxf(a3 + bb, 0.f) * wv;
    __syncthreads();
    for (int s = 128; s > 0; s >>= 1) {
        if (tid < s) {
            red[0][tid] += red[0][tid + s];
            red[1][tid] += red[1][tid + s];
            red[2][tid] += red[2][tid + s];
            red[3][tid] += red[3][tid + s];
        }
        __syncthreads();
    }
    if (tid < 4) {
        float z = red[tid][0] + b2[p];
        g_score[p][bg * 4 + tid] = 1.f / (1.f + expf(-z));
    }
}

// ---------------- 3) repack weights into fragment-packed tf32 layout ----------------
// f2s: g_wB[slot] as [dt(8)][kt(160)][4096-frag-chunk]; s2f: g_wS as [dt(8)][kt(32)][chunk]
__global__ void repack_kernel(const float* __restrict__ f2s_w, const float* __restrict__ s2f_w) {
    __shared__ int s_sel;
    __shared__ float s_score[32];
    long long idx = (long long)blockIdx.x * blockDim.x + threadIdx.x;
    const long long per_slot = 5LL * 1024 * 1024;      // 8*160*4096
    int tid = threadIdx.x;
    if (idx < 2 * per_slot) {
        int slot = (int)(idx / per_slot);
        BLOCK_SELECT(slot + 2, tid, s_sel, s_score);
        int sel = s_sel;
        if (sel < 0) return;
        int widx = sel * 2 + slot;
        long long r = idx - (long long)slot * per_slot;
        int dt = (int)(r / 655360);                    // 160*4096
        int r2 = (int)(r % 655360);
        int kt = r2 >> 12, q = r2 & 4095;
        int ks = q >> 10, kh = (q >> 9) & 1, wn = (q >> 8) & 1;
        int grp = (q >> 5) & 7, tg = (q >> 3) & 3, sl = (q >> 2) & 1, n4 = q & 3;
        int niq = sl ^ (grp & 1);                      // conflict-free placement
        int dout = dt * 128 + wn * 64 + (niq * 4 + n4) * 8 + grp;
        int k = kt * 32 + ks * 8 + kh * 4 + tg;
        int tap = k >> 10, din = k & 1023;
        g_wB[slot][r] = to_tf32(f2s_w[(((long long)widx * 1024 + dout) * 1024 + din) * 5 + tap]);
    } else {
        __shared__ int s_sel1;
        BLOCK_SELECT(0, tid, s_sel, s_score);
        BLOCK_SELECT(1, tid, s_sel1, s_score);
        if (s_sel < 0 && s_sel1 < 0) return;
        long long r = idx - 2 * per_slot;
        if (r >= 1024 * 1024) return;
        int dt = (int)(r >> 17);                       // 32*4096
        int r2 = (int)(r & 131071);
        int kt = r2 >> 12, q = r2 & 4095;
        int ks = q >> 10, kh = (q >> 9) & 1, wn = (q >> 8) & 1;
        int grp = (q >> 5) & 7, tg = (q >> 3) & 3, sl = (q >> 2) & 1, n4 = q & 3;
        int niq = sl ^ (grp & 1);
        int dout = dt * 128 + wn * 64 + (niq * 4 + n4) * 8 + grp;
        int k = kt * 32 + ks * 8 + kh * 4 + tg;
        g_wS[r] = to_tf32(s2f_w[(size_t)dout * 1024 + k]);
    }
}

// ---------------- fragment load + MMA for one 8-K quarter-stage (64n x 64d warp tile) --------
__device__ __forceinline__ void frag_mma_ks(uint32_t al, uint32_t bb, int ks, uint32_t sw16,
                                            float (&acc)[4][8][4]) {
    uint32_t A[4][4];
    #pragma unroll
    for (int m = 0; m < 4; ++m) LDSM4(A[m], al + m * 2304 + ks * 32);   // 16 rows * 144 B
    uint32_t b2 = bb + ks * 4096;
    uint32_t bf0[4], bf1[4], bf2[4], bf3[4];
    LDS128(bf0, b2 + sw16);               // kh0 niq0
    LDS128(bf1, b2 + (sw16 ^ 16));        // kh0 niq1
    LDS128(bf2, b2 + 2048 + sw16);        // kh1 niq0
    LDS128(bf3, b2 + 2048 + (sw16 ^ 16)); // kh1 niq1
    #pragma unroll
    for (int ni = 0; ni < 4; ++ni)
        #pragma unroll
        for (int m = 0; m < 4; ++m) {
            mma_tf32(acc[m][ni], A[m][0], A[m][1], A[m][2], A[m][3], bf0[ni], bf2[ni]);
            mma_tf32(acc[m][ni + 4], A[m][0], A[m][1], A[m][2], A[m][3], bf1[ni], bf3[ni]);
        }
}

// ---------------- 4) merged GEMM kernel: z=slot (0,1 -> s2f; 2,3 -> f2s) ----------------
__global__ __launch_bounds__(128, 2)
void gemm_all(const float* __restrict__ f0, const float* __restrict__ f1,
              const float* __restrict__ f2, const float* __restrict__ f3,
              const float* __restrict__ bias, float* __restrict__ outbase) {
    int z = blockIdx.z;
    int tid = threadIdx.x;
    __shared__ int s_sel;
    __shared__ float s_score[32];
    BLOCK_SELECT(z, tid, s_sel, s_score);
    int sel = s_sel;
    int n0 = blockIdx.x * 128, dt = blockIdx.y;

    extern __shared__ __align__(16) float dsm[];
    uint32_t sbA = smem_u32(dsm);
    uint32_t sbB = sbA + NSTAGE * ASTAGE;

    int wid = tid >> 5, lane = tid & 31;
    int wm = wid & 1, wn = wid >> 1;
    int grp = lane >> 2, tg = lane & 3;
    int q = lane >> 3, rr = lane & 7;
    uint32_t a_lm = sbA + (uint32_t)((wm * 64 + (q & 1) * 8 + rr) * 36 + (q >> 1) * 4) * 4;
    uint32_t b_base = sbB + (uint32_t)(wn * 256 + grp * 32 + tg * 8) * 4;
    uint32_t sw16 = (uint32_t)((grp & 1) << 4);

    // A-load: thread tid handles row tid, 8 chunks of 16B (32 floats)
    uint32_t adst = sbA + (uint32_t)(tid * 36) * 4;
    // B-load: thread tid handles chunks tid + 128*c (8 chunks)
    uint32_t bdst = sbB + (uint32_t)tid * 16;

    float acc[4][8][4];
    #pragma unroll
    for (int a = 0; a < 4; ++a)
        #pragma unroll
        for (int b = 0; b < 8; ++b)
            #pragma unroll
            for (int c = 0; c < 4; ++c) acc[a][b][c] = 0.f;

    if (z < 2) {                              // ---------- s2f ----------
        if (sel < 0) return;
        const float* X = (sel == 3) ? f3 : f2;
        float* Y = g_y[z];
        const float* bsrc0 = g_wS + (size_t)dt * 131072;
        const float* aps = X + (size_t)(n0 + tid) * 1024;
        const int KT = 32;
        #define S2F_LDA(kt, st) do { \
            const float* a_ = aps + (kt) * 32; \
            uint32_t ad_ = adst + (st) * ASTAGE; \
            _Pragma("unroll") \
            for (int c_ = 0; c_ < 8; ++c_) cp16(ad_ + c_ * 16, a_ + c_ * 4, 16); \
        } while (0)
        #define S2F_LDB(kt, st) do { \
            const float* b_ = bsrc0 + (size_t)(kt) * 4096 + tid * 4; \
            uint32_t bd_ = bdst + (st) * BSTAGE; \
            _Pragma("unroll") \
            for (int c_ = 0; c_ < 8; ++c_) cp16(bd_ + c_ * 2048, b_ + c_ * 512, 16); \
        } while (0)
        S2F_LDA(0, 0); S2F_LDB(0, 0); cp_commit();
        S2F_LDA(1, 1); S2F_LDB(1, 1); cp_commit();
        int s = 0, ps = 2;
        for (int kt = 0; kt < KT; ++kt) {
            cp_wait<1>();
            __syncthreads();
            uint32_t al = a_lm + s * ASTAGE, bb = b_base + s * BSTAGE;
            int pk = kt + 2;
            frag_mma_ks(al, bb, 0, sw16, acc);
            frag_mma_ks(al, bb, 1, sw16, acc);
            if (pk < KT) { S2F_LDA(pk, ps); S2F_LDB(pk, ps); }
            cp_commit();
            frag_mma_ks(al, bb, 2, sw16, acc);
            frag_mma_ks(al, bb, 3, sw16, acc);
            s = (s == 2) ? 0 : s + 1;
            ps = (ps == 2) ? 0 : ps + 1;
        }
        #undef S2F_LDA
        #undef S2F_LDB
        int rbase = n0 + wm * 64 + grp;
        int cbase = dt * 128 + wn * 64 + 2 * tg;
        #pragma unroll
        for (int mi = 0; mi < 4; ++mi) {
            int r1 = rbase + mi * 16, r2 = r1 + 8;
            #pragma unroll
            for (int ni = 0; ni < 8; ++ni) {
                int c = cbase + ni * 8;
                float bz0 = bias[c], bz1 = bias[c + 1];
                *(float2*)(Y + (size_t)r1 * 1024 + c) = make_float2(acc[mi][ni][0] + bz0, acc[mi][ni][1] + bz1);
                *(float2*)(Y + (size_t)r2 * 1024 + c) = make_float2(acc[mi][ni][2] + bz0, acc[mi][ni][3] + bz1);
            }
        }
    } else {                                  // ---------- f2s ----------
        int slot = z - 2;
        const float* FJ = slot ? f3 : f2;
        float* O = outbase + (slot ? (size_t)37748736 : (size_t)33554432);
        if (sel < 0) {                        // pass-through copy of 128x128 tile
            for (int i = tid; i < 128 * 32; i += 128) {
                int r = i >> 5, c4 = i & 31;
                size_t off = (size_t)(n0 + r) * 1024 + dt * 128 + c4 * 4;
                *(float4*)(O + off) = *(const float4*)(FJ + off);
            }
            return;
        }
        const float* X = (sel == 1) ? f1 : f0;   // [512][32][1024]
        const float* bsrc0 = g_wB[slot] + (size_t)dt * 655360;
        int nA = n0 + tid;
        int tf = 4 * (nA >> 5) - 2;
        const float* ab = X + (size_t)(nA & 31) * 1024;
        const int KT = 160;
        #define F2S_LDA(kt, st) do { \
            int tap_ = (kt) >> 5, din0_ = ((kt) & 31) << 5; \
            int t_ = tf + tap_; \
            const float* s_ = (t_ >= 0) ? (ab + (size_t)t_ * 32768 + din0_) : (const float*)X; \
            int ok_ = (t_ >= 0) ? 16 : 0; \
            uint32_t ad_ = adst + (st) * ASTAGE; \
            _Pragma("unroll") \
            for (int c_ = 0; c_ < 8; ++c_) cp16(ad_ + c_ * 16, s_ + c_ * 4, ok_); \
        } while (0)
        #define F2S_LDB(kt, st) do { \
            const float* b_ = bsrc0 + (size_t)(kt) * 4096 + tid * 4; \
            uint32_t bd_ = bdst + (st) * BSTAGE; \
            _Pragma("unroll") \
            for (int c_ = 0; c_ < 8; ++c_) cp16(bd_ + c_ * 2048, b_ + c_ * 512, 16); \
        } while (0)
        F2S_LDA(0, 0); F2S_LDB(0, 0); cp_commit();
        F2S_LDA(1, 1); F2S_LDB(1, 1); cp_commit();
        int s = 0, ps = 2;
        for (int kt = 0; kt < KT; ++kt) {
            cp_wait<1>();
            __syncthreads();
            uint32_t al = a_lm + s * ASTAGE, bb = b_base + s * BSTAGE;
            int pk = kt + 2;
            frag_mma_ks(al, bb, 0, sw16, acc);
            frag_mma_ks(al, bb, 1, sw16, acc);
            if (pk < KT) { F2S_LDA(pk, ps); F2S_LDB(pk, ps); }
            cp_commit();
            frag_mma_ks(al, bb, 2, sw16, acc);
            frag_mma_ks(al, bb, 3, sw16, acc);
            s = (s == 2) ? 0 : s + 1;
            ps = (ps == 2) ? 0 : ps + 1;
        }
        #undef F2S_LDA
        #undef F2S_LDB
        int rbase = n0 + wm * 64 + grp;
        int cbase = dt * 128 + wn * 64 + 2 * tg;
        #pragma unroll
        for (int mi = 0; mi < 4; ++mi) {
            int r1 = rbase + mi * 16, r2 = r1 + 8;
            float s1 = s_score[r1 & 31];
            float s2v = s_score[r2 & 31];
            #pragma unroll
            for (int ni = 0; ni < 8; ++ni) {
                int c = cbase + ni * 8;
                float2 b1 = *(const float2*)(FJ + (size_t)r1 * 1024 + c);
                float2 b2 = *(const float2*)(FJ + (size_t)r2 * 1024 + c);
                *(float2*)(O + (size_t)r1 * 1024 + c) =
                    make_float2(b1.x + s1 * acc[mi][ni][0], b1.y + s1 * acc[mi][ni][1]);
                *(float2*)(O + (size_t)r2 * 1024 + c) =
                    make_float2(b2.x + s2v * acc[mi][ni][2], b2.y + s2v * acc[mi][ni][3]);
            }
        }
    }
}

// ---------------- 5) fast outputs: upsample + gated residual ----------------
__global__ void upsample_kernel(const float* __restrict__ f0, const float* __restrict__ f1,
                                float* __restrict__ out) {
    int slot = blockIdx.y;
    __shared__ int s_sel;
    __shared__ float s_score[32];
    BLOCK_SELECT(slot, threadIdx.x, s_sel, s_score);
    const float* FJ = slot ? f1 : f0;
    float* O = out + (size_t)slot * 16777216;
    int idx4 = blockIdx.x * blockDim.x + threadIdx.x;
    if (idx4 >= 512 * 32 * 256) return;
    float4 base = ((const float4*)FJ)[idx4];
    float4 res = base;
    if (s_sel >= 0) {
        int t = idx4 / (32 * 256);
        int rem = idx4 % (32 * 256);
        int b = rem >> 8;
        float s = s_score[b];
        float srcp = (t + 0.5f) * 0.25f - 0.5f;
        srcp = fminf(fmaxf(srcp, 0.f), 127.f);
        int i0 = (int)floorf(srcp);
        int i1 = min(i0 + 1, 127);
        float wgt = srcp - (float)i0;
        const float4* yp = (const float4*)g_y[slot];
        float4 a = yp[i0 * (32 * 256) + rem];
        float4 c = yp[i1 * (32 * 256) + rem];
        res.x = base.x + s * ((1.f - wgt) * a.x + wgt * c.x);
        res.y = base.y + s * ((1.f - wgt) * a.y + wgt * c.y);
        res.z = base.z + s * ((1.f - wgt) * a.z + wgt * c.z);
        res.w = base.w + s * ((1.f - wgt) * a.w + wgt * c.w);
    }
    ((float4*)O)[idx4] = res;
}

// ---------------- launch ----------------
extern "C" void kernel_launch(void* const* d_in, const int* in_sizes, int n_in,
                              void* d_out, int out_size) {
    (void)in_sizes; (void)n_in; (void)out_size;
    const float* f0 = (const float*)d_in[0];
    const float* f1 = (const float*)d_in[1];
    const float* f2 = (const float*)d_in[2];
    const float* f3 = (const float*)d_in[3];
    const float* w1 = (const float*)d_in[4];
    const float* b1 = (const float*)d_in[5];
    const float* w2 = (const float*)d_in[6];
    const float* b2 = (const float*)d_in[7];
    const float* s2f_w = (const float*)d_in[8];
    const float* s2f_b = (const float*)d_in[9];
    const float* f2s_w = (const float*)d_in[10];
    float* out = (float*)d_out;

    cudaFuncSetAttribute(gemm_all, cudaFuncAttributeMaxDynamicSharedMemorySize, GSMEM);

    means_kernel<<<dim3(128, 4), 256>>>(f0, f1, f2, f3);                  // 0
    mlp_kernel<<<dim3(8, 8), 256>>>(w1, b1, w2, b2);                      // 1
    repack_kernel<<<45056, 256>>>(f2s_w, s2f_w);                          // 2
    gemm_all<<<dim3(32, 8, 4), 128, GSMEM>>>(f0, f1, f2, f3, s2f_b, out); // 3 <- ncu capture
    upsample_kernel<<<dim3(16384, 2), 256>>>(f0, f1, out);                // 4
}

// round 11
// speedup vs baseline: 1.3051x; 1.3051x over previous
#include <cuda_runtime.h>
#include <math.h>
#include <stdint.h>

// Shapes: T_FAST=512, T_SLOW=128, B=32, D=1024, H=256
// Inputs: 0..3 feat[T,B,D] f32; 4 mlp_w1[16,2048,256]; 5 mlp_b1[16,256];
// 6 mlp_w2[16,256,1]; 7 mlp_b2[16,1]; 8 s2f_w[1024,1024,1]; 9 s2f_b[1024];
// 10 f2s_w[4,1024,1024,5]
// Output: concat(out0[512,32,1024], out1, out2[128,32,1024], out3) f32

#define BATCH 32
#define DDIM  1024

// ---------------- scratch ----------------
static __device__ float g_means[4][BATCH][DDIM];
static __device__ float g_score[16][BATCH];
static __device__ __align__(128) float g_y[2][128 * BATCH * DDIM];   // s2f out, 33.5 MB
static __device__ __align__(128) float g_wB[2][1024 * 5120];         // f2s W fragment-packed, 42 MB
static __device__ __align__(128) float g_wS[1024 * 1024];            // s2f W fragment-packed, 4 MB

__constant__ int c_api[8] = {2, 2, 3, 3, 0, 0, 1, 1};
__constant__ int c_apj[8] = {0, 1, 0, 1, 2, 3, 2, 3};

// ---------------- helpers ----------------
__device__ __forceinline__ float to_tf32(float x) {
    uint32_t u; asm("cvt.rna.tf32.f32 %0, %1;" : "=r"(u) : "f"(x));
    return __uint_as_float(u);
}
__device__ __forceinline__ uint32_t smem_u32(const void* p) {
    return (uint32_t)__cvta_generic_to_shared(p);
}
__device__ __forceinline__ void cp16(uint32_t dst, const void* src, int sz) {
    asm volatile("cp.async.ca.shared.global [%0], [%1], 16, %2;" :: "r"(dst), "l"(src), "r"(sz));
}
__device__ __forceinline__ void cp_commit() { asm volatile("cp.async.commit_group;"); }
template <int N> __device__ __forceinline__ void cp_wait() {
    asm volatile("cp.async.wait_group %0;" :: "n"(N));
}
__device__ __forceinline__ void mma_tf32(float (&c)[4], uint32_t a0, uint32_t a1, uint32_t a2,
                                         uint32_t a3, uint32_t b0, uint32_t b1) {
    asm("mma.sync.aligned.m16n8k8.row.col.f32.tf32.tf32.f32 "
        "{%0,%1,%2,%3},{%4,%5,%6,%7},{%8,%9},{%0,%1,%2,%3};"
        : "+f"(c[0]), "+f"(c[1]), "+f"(c[2]), "+f"(c[3])
        : "r"(a0), "r"(a1), "r"(a2), "r"(a3), "r"(b0), "r"(b1));
}
#define LDSM4(r, a) \
    asm volatile("ldmatrix.sync.aligned.m8n8.x4.shared.b16 {%0,%1,%2,%3}, [%4];" \
        : "=r"((r)[0]), "=r"((r)[1]), "=r"((r)[2]), "=r"((r)[3]) : "r"(a))

// Per-block gate-selection recompute.
#define BLOCK_SELECT(jj, tid, s_sel, s_score) do { \
    if ((tid) < 32) { \
        int pA_, pB_, iA_, iB_; \
        if ((jj) < 2) { pA_ = 12 + (jj); iA_ = 3; pB_ = 8 + (jj); iB_ = 2; } \
        else          { pA_ = 4 + (jj);  iA_ = 1; pB_ = (jj);     iB_ = 0; } \
        float sA_ = g_score[pA_][(tid)], sB_ = g_score[pB_][(tid)]; \
        float mA_ = sA_, mB_ = sB_; \
        for (int o_ = 16; o_ > 0; o_ >>= 1) { \
            mA_ += __shfl_xor_sync(0xffffffffu, mA_, o_); \
            mB_ += __shfl_xor_sync(0xffffffffu, mB_, o_); \
        } \
        bool cA_ = (mA_ * (1.f / 32.f)) >= 0.3f; \
        bool cB_ = (mB_ * (1.f / 32.f)) >= 0.3f; \
        if ((tid) == 0) s_sel = cA_ ? iA_ : (cB_ ? iB_ : -1); \
        s_score[(tid)] = cA_ ? sA_ : (cB_ ? sB_ : 0.f); \
    } \
    __syncthreads(); \
} while (0)

// GEMM tiling: CTA = 128 n x 128 dout, BK = 16, 128 threads (4 warps 2x2: wm=wid&1, wn=wid>>1)
// Warp tile 64n x 64d. A in smem via cp.async (6-stage ring, 2-ahead prefetch, LDSM reads).
// B loaded DIRECTLY from global into registers (LDG.128, double-buffered 1 k-tile ahead) —
// removes B's cp.async + LDS traffic from the LSU pipe entirely.
// A smem: [128 rows][20 floats] (16 used + 4 pad; stride 20 is LDSM conflict-free) = 10240 B/stage
// B global chunk per kt (2048 floats): [niq(1b)][ks(1b)][kh(1b)][wn(1b)][grp(3b)][tg(2b)][n4(2b)]
//   lane l=grp*4+tg reads float4 at l*4 floats (coalesced); niq +1024, ks +512, kh +256, wn +128
//   value = W[dout = wn*64 + (niq*4+n4)*8 + grp][k = ks*8 + kh*4 + tg]
#define ASTAGE 10240
#define NSTAGE 6
#define GSMEM  (NSTAGE * ASTAGE)

// ---------------- 1) means ----------------
__global__ void means_kernel(const float* __restrict__ f0, const float* __restrict__ f1,
                             const float* __restrict__ f2, const float* __restrict__ f3) {
    int z = blockIdx.y;
    const float* f = (z == 0) ? f0 : (z == 1) ? f1 : (z == 2) ? f2 : f3;
    int T = (z < 2) ? 512 : 128;
    int idx = blockIdx.x * blockDim.x + threadIdx.x;
    if (idx >= BATCH * DDIM) return;
    float s0 = 0.f, s1 = 0.f, s2 = 0.f, s3 = 0.f;
    const float* p = f + idx;
    const int STRIDE = BATCH * DDIM;
    #pragma unroll 4
    for (int t = 0; t < T; t += 4) {
        s0 += p[(size_t)(t + 0) * STRIDE];
        s1 += p[(size_t)(t + 1) * STRIDE];
        s2 += p[(size_t)(t + 2) * STRIDE];
        s3 += p[(size_t)(t + 3) * STRIDE];
    }
    (&g_means[z][0][0])[idx] = ((s0 + s1) + (s2 + s3)) * (1.0f / (float)T);
}

// ---------------- 2) pair-gate MLPs -> g_score ----------------
__global__ void mlp_kernel(const float* __restrict__ w1, const float* __restrict__ b1,
                           const float* __restrict__ w2, const float* __restrict__ b2) {
    __shared__ float vec[4][2048];
    __shared__ float red[4][256];
    int pi = blockIdx.x, bg = blockIdx.y;
    int i = c_api[pi], j = c_apj[pi];
    int p = i * 4 + j;
    int tid = threadIdx.x;
    for (int q = 0; q < 4; ++q) {
        int b = bg * 4 + q;
        for (int k = tid; k < 2048; k += 256)
            vec[q][k] = (k < 1024) ? g_means[i][b][k] : g_means[j][b][k - 1024];
    }
    __syncthreads();
    const float* w1p = w1 + (size_t)p * 2048 * 256 + tid;
    float a0 = 0.f, a1 = 0.f, a2 = 0.f, a3 = 0.f;
    #pragma unroll 4
    for (int k = 0; k < 2048; ++k) {
        float w = w1p[(size_t)k * 256];
        a0 = fmaf(vec[0][k], w, a0);
        a1 = fmaf(vec[1][k], w, a1);
        a2 = fmaf(vec[2][k], w, a2);
        a3 = fmaf(vec[3][k], w, a3);
    }
    float bb = b1[p * 256 + tid];
    float wv = w2[p * 256 + tid];
    red[0][tid] = fmaxf(a0 + bb, 0.f) * wv;
    red[1][tid] = fmaxf(a1 + bb, 0.f) * wv;
    red[2][tid] = fmaxf(a2 + bb, 0.f) * wv;
    red[3][tid] = fmaxf(a3 + bb, 0.f) * wv;
    __syncthreads();
    for (int s = 128; s > 0; s >>= 1) {
        if (tid < s) {
            red[0][tid] += red[0][tid + s];
            red[1][tid] += red[1][tid + s];
            red[2][tid] += red[2][tid + s];
            red[3][tid] += red[3][tid + s];
        }
        __syncthreads();
    }
    if (tid < 4) {
        float z = red[tid][0] + b2[p];
        g_score[p][bg * 4 + tid] = 1.f / (1.f + expf(-z));
    }
}

// ---------------- 3) repack weights into lane-linear fragment layout ----------------
// f2s: g_wB[slot] as [dt(8)][kt(320)][2048-chunk]; s2f: g_wS as [dt(8)][kt(64)][chunk]
__global__ void repack_kernel(const float* __restrict__ f2s_w, const float* __restrict__ s2f_w) {
    __shared__ int s_sel;
    __shared__ float s_score[32];
    long long idx = (long long)blockIdx.x * blockDim.x + threadIdx.x;
    const long long per_slot = 5LL * 1024 * 1024;      // 8*320*2048
    int tid = threadIdx.x;
    if (idx < 2 * per_slot) {
        int slot = (int)(idx / per_slot);
        BLOCK_SELECT(slot + 2, tid, s_sel, s_score);
        int sel = s_sel;
        if (sel < 0) return;
        int widx = sel * 2 + slot;
        long long r = idx - (long long)slot * per_slot;
        int dt = (int)(r / 655360);                    // 320*2048
        int r2 = (int)(r % 655360);
        int kt = r2 >> 11, q = r2 & 2047;
        int niq = (q >> 10) & 1, ks = (q >> 9) & 1, kh = (q >> 8) & 1, wn = (q >> 7) & 1;
        int grp = (q >> 4) & 7, tg = (q >> 2) & 3, n4 = q & 3;
        int dout = dt * 128 + wn * 64 + (niq * 4 + n4) * 8 + grp;
        int k = kt * 16 + ks * 8 + kh * 4 + tg;
        int tap = k >> 10, din = k & 1023;
        g_wB[slot][r] = to_tf32(f2s_w[(((long long)widx * 1024 + dout) * 1024 + din) * 5 + tap]);
    } else {
        __shared__ int s_sel1;
        BLOCK_SELECT(0, tid, s_sel, s_score);
        BLOCK_SELECT(1, tid, s_sel1, s_score);
        if (s_sel < 0 && s_sel1 < 0) return;
        long long r = idx - 2 * per_slot;
        if (r >= 1024 * 1024) return;
        int dt = (int)(r >> 17);                       // 64*2048
        int r2 = (int)(r & 131071);
        int kt = r2 >> 11, q = r2 & 2047;
        int niq = (q >> 10) & 1, ks = (q >> 9) & 1, kh = (q >> 8) & 1, wn = (q >> 7) & 1;
        int grp = (q >> 4) & 7, tg = (q >> 2) & 3, n4 = q & 3;
        int dout = dt * 128 + wn * 64 + (niq * 4 + n4) * 8 + grp;
        int k = kt * 16 + ks * 8 + kh * 4 + tg;
        g_wS[r] = to_tf32(s2f_w[(size_t)dout * 1024 + k]);
    }
}

// ---------------- B fragment fetch: 8 x LDG.128 per k-tile into registers ----------------
__device__ __forceinline__ void ldgB(const float* __restrict__ g, float4 (&v)[8]) {
    #pragma unroll
    for (int ks = 0; ks < 2; ++ks)
        #pragma unroll
        for (int kh = 0; kh < 2; ++kh)
            #pragma unroll
            for (int niq = 0; niq < 2; ++niq)
                v[ks * 4 + kh * 2 + niq] =
                    *(const float4*)(g + niq * 1024 + ks * 512 + kh * 256);
}

// ---------------- fragment MMA for one 8-K half-tile (64n x 64d warp tile) ----------------
// bv[0]=kh0niq0, bv[1]=kh0niq1, bv[2]=kh1niq0, bv[3]=kh1niq1
__device__ __forceinline__ void frag_mma_ks(uint32_t al, const float4* bv, int ks,
                                            float (&acc)[4][8][4]) {
    uint32_t A[4][4];
    #pragma unroll
    for (int m = 0; m < 4; ++m) LDSM4(A[m], al + m * 1280 + ks * 32);
    const float* f00 = (const float*)&bv[0];
    const float* f01 = (const float*)&bv[1];
    const float* f10 = (const float*)&bv[2];
    const float* f11 = (const float*)&bv[3];
    #pragma unroll
    for (int ni = 0; ni < 4; ++ni) {
        uint32_t b00 = __float_as_uint(f00[ni]);
        uint32_t b10 = __float_as_uint(f10[ni]);
        uint32_t b01 = __float_as_uint(f01[ni]);
        uint32_t b11 = __float_as_uint(f11[ni]);
        #pragma unroll
        for (int m = 0; m < 4; ++m) {
            mma_tf32(acc[m][ni], A[m][0], A[m][1], A[m][2], A[m][3], b00, b10);
            mma_tf32(acc[m][ni + 4], A[m][0], A[m][1], A[m][2], A[m][3], b01, b11);
        }
    }
}

// ---------------- 4) merged GEMM kernel: z=0,1 -> f2s (long, launched first); z=2,3 -> s2f --
__global__ __launch_bounds__(128, 2)
void gemm_all(const float* __restrict__ f0, const float* __restrict__ f1,
              const float* __restrict__ f2, const float* __restrict__ f3,
              const float* __restrict__ bias, float* __restrict__ outbase) {
    int z = blockIdx.z;
    int tid = threadIdx.x;
    bool is_f2s = (z < 2);
    int jj = is_f2s ? (z + 2) : (z - 2);     // output slot index 0..3
    __shared__ int s_sel;
    __shared__ float s_score[32];
    BLOCK_SELECT(jj, tid, s_sel, s_score);
    int sel = s_sel;
    int n0 = blockIdx.x * 128, dt = blockIdx.y;

    extern __shared__ __align__(16) float dsm[];
    uint32_t sbA = smem_u32(dsm);

    int wid = tid >> 5, lane = tid & 31;
    int wm = wid & 1, wn = wid >> 1;
    int grp = lane >> 2, tg = lane & 3;
    int q = lane >> 3, rr = lane & 7;
    uint32_t a_lm = sbA + (uint32_t)((wm * 64 + (q & 1) * 8 + rr) * 20 + (q >> 1) * 4) * 4;
    uint32_t adst = sbA + (uint32_t)(tid * 20) * 4;

    float acc[4][8][4];
    #pragma unroll
    for (int a = 0; a < 4; ++a)
        #pragma unroll
        for (int b = 0; b < 8; ++b)
            #pragma unroll
            for (int c = 0; c < 4; ++c) acc[a][b][c] = 0.f;

    float4 bv0[8], bv1[8];

    if (!is_f2s) {                            // ---------- s2f ----------
        int slot = z - 2;
        if (sel < 0) return;
        const float* X = (sel == 3) ? f3 : f2;
        float* Y = g_y[slot];
        const float* gb = g_wS + (size_t)dt * 131072 + wn * 128 + lane * 4;
        const float* aps = X + (size_t)(n0 + tid) * 1024;
        const int KT = 64;
        #define S2F_LDA(kt, st) do { \
            const float* a_ = aps + (kt) * 16; \
            uint32_t ad_ = adst + (st) * ASTAGE; \
            cp16(ad_, a_, 16); cp16(ad_ + 16, a_ + 4, 16); \
            cp16(ad_ + 32, a_ + 8, 16); cp16(ad_ + 48, a_ + 12, 16); \
        } while (0)
        ldgB(gb, bv0);
        S2F_LDA(0, 0); cp_commit();
        S2F_LDA(1, 1); cp_commit();
        S2F_LDA(2, 2); cp_commit();
        S2F_LDA(3, 3); cp_commit();
        S2F_LDA(4, 4); cp_commit();
        int s = 0, ps = 5;
        for (int kt = 0; kt < KT; kt += 2) {
            if (kt + 1 < KT) ldgB(gb + (size_t)(kt + 1) * 2048, bv1);
            cp_wait<4>();
            __syncthreads();
            {
                uint32_t al = a_lm + s * ASTAGE;
                frag_mma_ks(al, bv0 + 0, 0, acc);
                frag_mma_ks(al, bv0 + 4, 1, acc);
            }
            if (kt + 5 < KT) S2F_LDA(kt + 5, ps);
            cp_commit();
            s = (s == 5) ? 0 : s + 1; ps = (ps == 5) ? 0 : ps + 1;
            if (kt + 2 < KT) ldgB(gb + (size_t)(kt + 2) * 2048, bv0);
            cp_wait<4>();
            __syncthreads();
            {
                uint32_t al = a_lm + s * ASTAGE;
                frag_mma_ks(al, bv1 + 0, 0, acc);
                frag_mma_ks(al, bv1 + 4, 1, acc);
            }
            if (kt + 6 < KT) S2F_LDA(kt + 6, ps);
            cp_commit();
            s = (s == 5) ? 0 : s + 1; ps = (ps == 5) ? 0 : ps + 1;
        }
        #undef S2F_LDA
        int rbase = n0 + wm * 64 + grp;
        int cbase = dt * 128 + wn * 64 + 2 * tg;
        #pragma unroll
        for (int mi = 0; mi < 4; ++mi) {
            int r1 = rbase + mi * 16, r2 = r1 + 8;
            #pragma unroll
            for (int ni = 0; ni < 8; ++ni) {
                int c = cbase + ni * 8;
                float bz0 = bias[c], bz1 = bias[c + 1];
                *(float2*)(Y + (size_t)r1 * 1024 + c) = make_float2(acc[mi][ni][0] + bz0, acc[mi][ni][1] + bz1);
                *(float2*)(Y + (size_t)r2 * 1024 + c) = make_float2(acc[mi][ni][2] + bz0, acc[mi][ni][3] + bz1);
            }
        }
    } else {                                  // ---------- f2s ----------
        int slot = z;
        const float* FJ = slot ? f3 : f2;
        float* O = outbase + (slot ? (size_t)37748736 : (size_t)33554432);
        if (sel < 0) {                        // pass-through copy of 128x128 tile
            for (int i = tid; i < 128 * 32; i += 128) {
                int r = i >> 5, c4 = i & 31;
                size_t off = (size_t)(n0 + r) * 1024 + dt * 128 + c4 * 4;
                *(float4*)(O + off) = *(const float4*)(FJ + off);
            }
            return;
        }
        const float* X = (sel == 1) ? f1 : f0;   // [512][32][1024]
        const float* gb = g_wB[slot] + (size_t)dt * 655360 + wn * 128 + lane * 4;
        int nA = n0 + tid;
        int tf = 4 * (nA >> 5) - 2;
        const float* ab = X + (size_t)(nA & 31) * 1024;
        const int KT = 320;
        #define F2S_LDA(kt, st) do { \
            int tap_ = (kt) >> 6, din0_ = ((kt) & 63) << 4; \
            int t_ = tf + tap_; \
            const float* s_ = (t_ >= 0) ? (ab + (size_t)t_ * 32768 + din0_) : (const float*)X; \
            int ok_ = (t_ >= 0) ? 16 : 0; \
            uint32_t ad_ = adst + (st) * ASTAGE; \
            cp16(ad_, s_, ok_); cp16(ad_ + 16, s_ + 4, ok_); \
            cp16(ad_ + 32, s_ + 8, ok_); cp16(ad_ + 48, s_ + 12, ok_); \
        } while (0)
        ldgB(gb, bv0);
        F2S_LDA(0, 0); cp_commit();
        F2S_LDA(1, 1); cp_commit();
        F2S_LDA(2, 2); cp_commit();
        F2S_LDA(3, 3); cp_commit();
        F2S_LDA(4, 4); cp_commit();
        int s = 0, ps = 5;
        for (int kt = 0; kt < KT; kt += 2) {
            if (kt + 1 < KT) ldgB(gb + (size_t)(kt + 1) * 2048, bv1);
            cp_wait<4>();
            __syncthreads();
            {
                uint32_t al = a_lm + s * ASTAGE;
                frag_mma_ks(al, bv0 + 0, 0, acc);
                frag_mma_ks(al, bv0 + 4, 1, acc);
            }
            if (kt + 5 < KT) F2S_LDA(kt + 5, ps);
            cp_commit();
            s = (s == 5) ? 0 : s + 1; ps = (ps == 5) ? 0 : ps + 1;
            if (kt + 2 < KT) ldgB(gb + (size_t)(kt + 2) * 2048, bv0);
            cp_wait<4>();
            __syncthreads();
            {
                uint32_t al = a_lm + s * ASTAGE;
                frag_mma_ks(al, bv1 + 0, 0, acc);
                frag_mma_ks(al, bv1 + 4, 1, acc);
            }
            if (kt + 6 < KT) F2S_LDA(kt + 6, ps);
            cp_commit();
            s = (s == 5) ? 0 : s + 1; ps = (ps == 5) ? 0 : ps + 1;
        }
        #undef F2S_LDA
        int rbase = n0 + wm * 64 + grp;
        int cbase = dt * 128 + wn * 64 + 2 * tg;
        #pragma unroll
        for (int mi = 0; mi < 4; ++mi) {
            int r1 = rbase + mi * 16, r2 = r1 + 8;
            float s1 = s_score[r1 & 31];
            float s2v = s_score[r2 & 31];
            #pragma unroll
            for (int ni = 0; ni < 8; ++ni) {
                int c = cbase + ni * 8;
                float2 b1 = *(const float2*)(FJ + (size_t)r1 * 1024 + c);
                float2 b2 = *(const float2*)(FJ + (size_t)r2 * 1024 + c);
                *(float2*)(O + (size_t)r1 * 1024 + c) =
                    make_float2(b1.x + s1 * acc[mi][ni][0], b1.y + s1 * acc[mi][ni][1]);
                *(float2*)(O + (size_t)r2 * 1024 + c) =
                    make_float2(b2.x + s2v * acc[mi][ni][2], b2.y + s2v * acc[mi][ni][3]);
            }
        }
    }
}

// ---------------- 5) fast outputs: upsample + gated residual ----------------
__global__ void upsample_kernel(const float* __restrict__ f0, const float* __restrict__ f1,
                                float* __restrict__ out) {
    int slot = blockIdx.y;
    __shared__ int s_sel;
    __shared__ float s_score[32];
    BLOCK_SELECT(slot, threadIdx.x, s_sel, s_score);
    const float* FJ = slot ? f1 : f0;
    float* O = out + (size_t)slot * 16777216;
    int idx4 = blockIdx.x * blockDim.x + threadIdx.x;
    if (idx4 >= 512 * 32 * 256) return;
    float4 base = ((const float4*)FJ)[idx4];
    float4 res = base;
    if (s_sel >= 0) {
        int t = idx4 / (32 * 256);
        int rem = idx4 % (32 * 256);
        int b = rem >> 8;
        float s = s_score[b];
        float srcp = (t + 0.5f) * 0.25f - 0.5f;
        srcp = fminf(fmaxf(srcp, 0.f), 127.f);
        int i0 = (int)floorf(srcp);
        int i1 = min(i0 + 1, 127);
        float wgt = srcp - (float)i0;
        const float4* yp = (const float4*)g_y[slot];
        float4 a = yp[i0 * (32 * 256) + rem];
        float4 c = yp[i1 * (32 * 256) + rem];
        res.x = base.x + s * ((1.f - wgt) * a.x + wgt * c.x);
        res.y = base.y + s * ((1.f - wgt) * a.y + wgt * c.y);
        res.z = base.z + s * ((1.f - wgt) * a.z + wgt * c.z);
        res.w = base.w + s * ((1.f - wgt) * a.w + wgt * c.w);
    }
    ((float4*)O)[idx4] = res;
}

// ---------------- launch ----------------
extern "C" void kernel_launch(void* const* d_in, const int* in_sizes, int n_in,
                              void* d_out, int out_size) {
    (void)in_sizes; (void)n_in; (void)out_size;
    const float* f0 = (const float*)d_in[0];
    const float* f1 = (const float*)d_in[1];
    const float* f2 = (const float*)d_in[2];
    const float* f3 = (const float*)d_in[3];
    const float* w1 = (const float*)d_in[4];
    const float* b1 = (const float*)d_in[5];
    const float* w2 = (const float*)d_in[6];
    const float* b2 = (const float*)d_in[7];
    const float* s2f_w = (const float*)d_in[8];
    const float* s2f_b = (const float*)d_in[9];
    const float* f2s_w = (const float*)d_in[10];
    float* out = (float*)d_out;

    cudaFuncSetAttribute(gemm_all, cudaFuncAttributeMaxDynamicSharedMemorySize, GSMEM);

    means_kernel<<<dim3(128, 4), 256>>>(f0, f1, f2, f3);                  // 0
    mlp_kernel<<<dim3(8, 8), 256>>>(w1, b1, w2, b2);                      // 1
    repack_kernel<<<45056, 256>>>(f2s_w, s2f_w);                          // 2
    gemm_all<<<dim3(32, 8, 4), 128, GSMEM>>>(f0, f1, f2, f3, s2f_b, out); // 3 <- ncu capture
    upsample_kernel<<<dim3(16384, 2), 256>>>(f0, f1, out);                // 4
}